// round 12
// baseline (speedup 1.0000x reference)
#include <cuda_runtime.h>

#define D_  16
#define H_  128
#define W_  128
#define VOX 262144        // 16*128*128
#define CI  64
#define MAXACT 49152      // cap on active voxels (~39.3K expected)
#define PP  8192          // per-tap pair capacity (~5.9K expected)

// Packed fp32x2 FMA (Blackwell sm_100+; SASS FFMA2). Bitwise == 2x fmaf.
#define FMA2(d, xa, wb, cc) \
    asm("fma.rn.f32x2 %0, %1, %2, %3;" : "=l"(d) : "l"(xa), "l"(wb), "l"(cc))

// ---------------- static device scratch (rank-compacted, two live branches) ----------
__device__ __align__(16) float g_xT[(size_t)MAXACT * CI];
__device__ __align__(16) float g_t1a[(size_t)MAXACT * CI];
__device__ __align__(16) float g_t1b[(size_t)MAXACT * CI];
__device__ __align__(16) float g_ctrA[(size_t)MAXACT * 128];
__device__ __align__(16) float g_ctrB[(size_t)MAXACT * 128];
__device__ __align__(16) float g_poutA[(size_t)8 * PP * 128];
__device__ __align__(16) float g_poutB[(size_t)8 * PP * 128];
__device__ __align__(16) float g_sum[(size_t)MAXACT * 128];
// weights in vectorized layout: [tap][cin/4][cout][4]
__device__ __align__(16) float g_w1a[9 * CI * 64];
__device__ __align__(16) float g_w1b[9 * CI * 128];
__device__ __align__(16) float g_w2a[9 * CI * 64];
__device__ __align__(16) float g_w2b[9 * CI * 128];
__device__ int  g_rank[VOX];
__device__ int  g_active[MAXACT];
__device__ int  g_count;
__device__ int  g_pvin[3][8][PP];
__device__ int  g_inv[3][(size_t)MAXACT * 8];
__device__ int  g_pcount[3][8];

// ---------------- reset counters ----------------
__global__ void k_reset() {
    int i = threadIdx.x;
    if (i < 24) (&g_pcount[0][0])[i] = 0;
    if (i == 24) g_count = 0;
}

// ---------------- transpose x -> rank-compact channel-last, build rank map ----------------
__global__ void k_transpose(const float* __restrict__ x) {
    int v = blockIdx.x * blockDim.x + threadIdx.x;
    if (v >= VOX) return;
    bool act = false;
    float4 f[16];
    #pragma unroll
    for (int i = 0; i < 16; ++i) {
        float4 t;
        t.x = x[(size_t)(4 * i + 0) * VOX + v];
        t.y = x[(size_t)(4 * i + 1) * VOX + v];
        t.z = x[(size_t)(4 * i + 2) * VOX + v];
        t.w = x[(size_t)(4 * i + 3) * VOX + v];
        f[i] = t;
        act = act || (t.x != 0.f) || (t.y != 0.f) || (t.z != 0.f) || (t.w != 0.f);
    }
    unsigned ball = __ballot_sync(0xffffffffu, act);
    int rank = -1;
    if (act) {
        int lane = threadIdx.x & 31;
        int leader = __ffs(ball) - 1;
        int base = 0;
        if (lane == leader) base = atomicAdd(&g_count, __popc(ball));
        base = __shfl_sync(ball, base, leader);   // mask == participants: legal
        rank = base + __popc(ball & ((1u << lane) - 1));
        if (rank < MAXACT) {
            g_active[rank] = v;
            #pragma unroll
            for (int i = 0; i < 16; ++i)
                *reinterpret_cast<float4*>(&g_xT[(size_t)rank * CI + 4 * i]) = f[i];
        }
    }
    g_rank[v] = (rank >= 0 && rank < MAXACT) ? rank : -1;
}

// -------- merged: pair lists (grid x,y,z) + weight re-layout (folded by block id) -----
// Weight layout out: [tap][cin/4][cout][4]  (float4 per (cin/4, cout))
__device__ __forceinline__ void prep_slice(
    const float* __restrict__ s1a, const float* __restrict__ s1b,
    const float* __restrict__ s2a, const float* __restrict__ s2b,
    int idx)
{
    const int N64 = 9 * CI * 64, N128 = 9 * CI * 128;
    const float* src; float* dst; int CO; int k = idx;
    if (k < N64)               { src = s1a; dst = g_w1a; CO = 64; }
    else if ((k -= N64) < N128){ src = s1b; dst = g_w1b; CO = 128; }
    else if ((k -= N128) < N64){ src = s2a; dst = g_w2a; CO = 64; }
    else if ((k -= N64) < N128){ src = s2b; dst = g_w2b; CO = 128; }
    else return;
    int j   = k & 3;
    int co  = (k >> 2) % CO;
    int c4  = (k / (4 * CO)) & 15;
    int tap = k / (64 * CO);
    int cin = c4 * 4 + j;
    dst[k] = src[(co * CI + cin) * 9 + tap];
}

__global__ void __launch_bounds__(256) k_prep_pairs(
    const float* __restrict__ s1a, const float* __restrict__ s1b,
    const float* __restrict__ s2a, const float* __restrict__ s2b)
{
    __shared__ int s_w[8];
    __shared__ int s_base;
    int mode = blockIdx.y;
    int t8 = blockIdx.z;
    int i = blockIdx.x * 256 + threadIdx.x;
    int N = min(g_count, MAXACT);
    bool valid = i < N;
    int v = valid ? g_active[i] : 0;
    int d = v >> 14, h = (v >> 7) & 127, w = v & 127;
    int wid = threadIdx.x >> 5, lane = threadIdx.x & 31;

    int tap = t8 < 4 ? t8 : t8 + 1;
    int dd, dh, dw;
    if (mode == 0)      { dd = tap / 3 - 1; dh = tap % 3 - 1; dw = 0; }
    else if (mode == 1) { dd = 0;           dh = tap / 3 - 1; dw = tap % 3 - 1; }
    else                { dd = tap / 3 - 1; dh = 0;           dw = tap % 3 - 1; }
    int nd = d + dd, nh = h + dh, nw = w + dw;
    int r2 = -1;
    if (valid && nd >= 0 && nd < D_ && nh >= 0 && nh < H_ && nw >= 0 && nw < W_)
        r2 = g_rank[(nd << 14) | (nh << 7) | nw];
    unsigned ball = __ballot_sync(0xffffffffu, r2 >= 0);
    if (lane == 0) s_w[wid] = __popc(ball);
    __syncthreads();
    if (threadIdx.x == 0) {
        int tot = 0;
        #pragma unroll
        for (int k = 0; k < 8; ++k) { int c = s_w[k]; s_w[k] = tot; tot += c; }
        s_base = tot ? atomicAdd(&g_pcount[mode][t8], tot) : 0;
    }
    __syncthreads();
    int pos = -1;
    if (r2 >= 0) {
        pos = s_base + s_w[wid] + __popc(ball & ((1u << lane) - 1));
        if (pos >= 0 && pos < PP) g_pvin[mode][t8][pos] = r2;
        else pos = -1;
    }
    if (valid) g_inv[mode][(size_t)i * 8 + t8] = pos;

    // folded weight prep: linear block id < 864 handles 256 elems each
    int bid = blockIdx.x + gridDim.x * (blockIdx.y + 3 * blockIdx.z);
    const int PREP_TOTAL = 9 * CI * (64 + 128 + 64 + 128);   // 221184
    int pidx = bid * 256 + threadIdx.x;
    if (pidx < PREP_TOTAL) prep_slice(s1a, s1b, s2a, s2b, pidx);
}

// ---------- merged two-branch conv, flattened work queue over (tap, chunk) ----------
// grid = (NBLK, 2 branches); each block strides a linear chunk list; t8 8 = center.
template<int COUT, int MA, int MB>
__global__ void __launch_bounds__(COUT) k_convAB(
    const float* __restrict__ in0, const float* __restrict__ in1,
    const float* __restrict__ wA,  const float* __restrict__ wB,
    float* __restrict__ ctr0, float* __restrict__ ctr1,
    float* __restrict__ pout0, float* __restrict__ pout1)
{
    __shared__ __align__(16) float s_in[CI][32];
    __shared__ int s_vi[32];
    const int tid = threadIdx.x;
    const int branch = blockIdx.y;
    const int mode = branch ? MB : MA;
    const float* __restrict__ in = branch ? in1 : in0;
    const float* __restrict__ wT = branch ? wB : wA;
    float* __restrict__ ctr = branch ? ctr1 : ctr0;
    float* __restrict__ pout = branch ? pout1 : pout0;

    // per-tap chunk prefix (uniform across block)
    int cnt[9], off[10];
    #pragma unroll
    for (int t = 0; t < 8; ++t) cnt[t] = min(g_pcount[mode][t], PP);
    cnt[8] = min(g_count, MAXACT);
    off[0] = 0;
    #pragma unroll
    for (int t = 0; t < 9; ++t) off[t + 1] = off[t] + ((cnt[t] + 31) >> 5);
    const int T = off[9];

    for (int wk = blockIdx.x; wk < T; wk += gridDim.x) {
        int t8 = 0;
        #pragma unroll
        for (int t = 0; t < 8; ++t) if (wk >= off[t + 1]) t8 = t + 1;
        const bool center = (t8 == 8);
        const int tap = center ? 4 : (t8 < 4 ? t8 : t8 + 1);
        const int m = cnt[t8];
        const int base = (wk - off[t8]) * 32;
        const int nv = min(32, m - base);

        __syncthreads();   // protect prior iteration's s_in/s_vi reads
        if (tid < 32) {
            int r = 0;
            if (tid < nv) {
                if (center) r = base + tid;
                else {
                    r = g_pvin[mode][t8][base + tid];
                    r = min(max(r, 0), MAXACT - 1);
                }
            }
            s_vi[tid] = r;
        }
        __syncthreads();

        for (int e = tid; e < 32 * (CI / 4); e += COUT) {
            int slot = e & 31, q = e >> 5;
            float4 f = make_float4(0.f, 0.f, 0.f, 0.f);
            if (slot < nv)
                f = *reinterpret_cast<const float4*>(&in[(size_t)s_vi[slot] * CI + q * 4]);
            s_in[q * 4 + 0][slot] = f.x;
            s_in[q * 4 + 1][slot] = f.y;
            s_in[q * 4 + 2][slot] = f.z;
            s_in[q * 4 + 3][slot] = f.w;
        }
        __syncthreads();

        unsigned long long acc[16];
        #pragma unroll
        for (int j = 0; j < 16; ++j) acc[j] = 0ull;

        // vectorized weight loads: one LDG.128 per 4 cin
        const float4* __restrict__ w4 =
            reinterpret_cast<const float4*>(wT) + (size_t)tap * 16 * COUT + tid;
        union Q4 { float4 f4; unsigned long long u[2]; };
        #pragma unroll 2
        for (int c4 = 0; c4 < 16; ++c4) {
            float4 wv = w4[c4 * COUT];
            #pragma unroll
            for (int j = 0; j < 4; ++j) {
                float wc = (j == 0) ? wv.x : (j == 1) ? wv.y : (j == 2) ? wv.z : wv.w;
                unsigned long long w2;
                asm("mov.b64 %0, {%1, %1};" : "=l"(w2) : "f"(wc));
                const float4* r = reinterpret_cast<const float4*>(&s_in[c4 * 4 + j][0]);
                #pragma unroll
                for (int q = 0; q < 8; ++q) {
                    Q4 u; u.f4 = r[q];
                    FMA2(acc[q * 2 + 0], u.u[0], w2, acc[q * 2 + 0]);
                    FMA2(acc[q * 2 + 1], u.u[1], w2, acc[q * 2 + 1]);
                }
            }
        }

        union P2 { unsigned long long u; float f[2]; };
        if (center) {
            #pragma unroll
            for (int j = 0; j < 16; ++j) {
                P2 p; p.u = acc[j];
                int s0 = 2 * j;
                if (s0 + 0 < nv) ctr[(size_t)(base + s0 + 0) * COUT + tid] = p.f[0];
                if (s0 + 1 < nv) ctr[(size_t)(base + s0 + 1) * COUT + tid] = p.f[1];
            }
        } else {
            #pragma unroll
            for (int j = 0; j < 16; ++j) {
                P2 p; p.u = acc[j];
                int s0 = 2 * j;
                if (s0 + 0 < nv) pout[((size_t)t8 * PP + base + s0 + 0) * COUT + tid] = p.f[0];
                if (s0 + 1 < nv) pout[((size_t)t8 * PP + base + s0 + 1) * COUT + tid] = p.f[1];
            }
        }
    }
}

// ---------------- stage-a merged sum+GN+leaky: grid = (chunks, 2 branches) ----------
__global__ void __launch_bounds__(64) k_sumgnA(
    const float* __restrict__ ctr0, const float* __restrict__ ctr1,
    const float* __restrict__ pout0, const float* __restrict__ pout1,
    const int* __restrict__ invA, const int* __restrict__ invB,
    const float* __restrict__ gA, const float* __restrict__ bA,
    const float* __restrict__ gB, const float* __restrict__ bB,
    float* __restrict__ outA, float* __restrict__ outB)
{
    constexpr int COUT = 64, CPG = 2;
    __shared__ int s_inv[128];
    const int tid = threadIdx.x;
    const int branch = blockIdx.y;
    const int N = min(g_count, MAXACT);
    const int base = blockIdx.x * 16;
    if (base >= N) return;
    const int nv = min(16, N - base);
    const float* __restrict__ ctr = branch ? ctr1 : ctr0;
    const float* __restrict__ pout = branch ? pout1 : pout0;
    const int* __restrict__ inv = branch ? invB : invA;
    const float gam = (branch ? gB : gA)[tid];
    const float bet = (branch ? bB : bA)[tid];
    float* __restrict__ out = branch ? outB : outA;

    for (int e = tid; e < 128; e += COUT) {
        int s = e >> 3, t8e = e & 7;
        s_inv[e] = (s < nv) ? inv[(size_t)(base + s) * 8 + t8e] : -1;
    }
    __syncthreads();

    float a[16];
    #pragma unroll
    for (int s = 0; s < 16; ++s)
        a[s] = (s < nv) ? ctr[(size_t)(base + s) * COUT + tid] : 0.f;

    #pragma unroll
    for (int t8 = 0; t8 < 8; ++t8) {
        #pragma unroll
        for (int s = 0; s < 16; ++s) {
            int p = s_inv[s * 8 + t8];
            if (p >= 0 && p < PP)
                a[s] += pout[((size_t)t8 * PP + p) * COUT + tid];
        }
    }

    #pragma unroll
    for (int s = 0; s < 16; ++s) {
        float sum = a[s];
        #pragma unroll
        for (int off = 1; off < CPG; off <<= 1)
            sum += __shfl_xor_sync(0xffffffffu, sum, off);
        float mu = sum * (1.0f / CPG);
        float dv = a[s] - mu;
        float vs = dv * dv;
        #pragma unroll
        for (int off = 1; off < CPG; off <<= 1)
            vs += __shfl_xor_sync(0xffffffffu, vs, off);
        float y = dv * rsqrtf(vs * (1.0f / CPG) + 1e-5f) * gam + bet;
        a[s] = (y > 0.f) ? y : 0.01f * y;   // leaky
    }

    #pragma unroll
    for (int s = 0; s < 16; ++s)
        if (s < nv) out[(size_t)(base + s) * COUT + tid] = a[s];
}

// ---------------- stage-b fused: both branches' sum+GN, write sum = y1+y2 ------------
__global__ void __launch_bounds__(128) k_sumgnB(
    const float* __restrict__ ctr0, const float* __restrict__ ctr1,
    const float* __restrict__ pout0, const float* __restrict__ pout1,
    const int* __restrict__ invA, const int* __restrict__ invB,
    const float* __restrict__ gA, const float* __restrict__ bA,
    const float* __restrict__ gB, const float* __restrict__ bB,
    float* __restrict__ out)
{
    constexpr int COUT = 128, CPG = 4;
    __shared__ int s_invA[128];
    __shared__ int s_invB[128];
    const int tid = threadIdx.x;
    const int N = min(g_count, MAXACT);
    const int base = blockIdx.x * 16;
    if (base >= N) return;
    const int nv = min(16, N - base);
    const float gam1 = gA[tid], bet1 = bA[tid];
    const float gam2 = gB[tid], bet2 = bB[tid];

    for (int e = tid; e < 128; e += COUT) {
        int s = e >> 3, t8e = e & 7;
        s_invA[e] = (s < nv) ? invA[(size_t)(base + s) * 8 + t8e] : -1;
        s_invB[e] = (s < nv) ? invB[(size_t)(base + s) * 8 + t8e] : -1;
    }
    __syncthreads();

    float a1[16], a2[16];
    #pragma unroll
    for (int s = 0; s < 16; ++s) {
        a1[s] = (s < nv) ? ctr0[(size_t)(base + s) * COUT + tid] : 0.f;
        a2[s] = (s < nv) ? ctr1[(size_t)(base + s) * COUT + tid] : 0.f;
    }

    #pragma unroll
    for (int t8 = 0; t8 < 8; ++t8) {
        #pragma unroll
        for (int s = 0; s < 16; ++s) {
            int p = s_invA[s * 8 + t8];
            if (p >= 0 && p < PP)
                a1[s] += pout0[((size_t)t8 * PP + p) * COUT + tid];
            int q = s_invB[s * 8 + t8];
            if (q >= 0 && q < PP)
                a2[s] += pout1[((size_t)t8 * PP + q) * COUT + tid];
        }
    }

    #pragma unroll
    for (int s = 0; s < 16; ++s) {
        float y1, y2;
        {
            float sum = a1[s];
            #pragma unroll
            for (int off = 1; off < CPG; off <<= 1)
                sum += __shfl_xor_sync(0xffffffffu, sum, off);
            float mu = sum * (1.0f / CPG);
            float dv = a1[s] - mu;
            float vs = dv * dv;
            #pragma unroll
            for (int off = 1; off < CPG; off <<= 1)
                vs += __shfl_xor_sync(0xffffffffu, vs, off);
            y1 = dv * rsqrtf(vs * (1.0f / CPG) + 1e-5f) * gam1 + bet1;
        }
        {
            float sum = a2[s];
            #pragma unroll
            for (int off = 1; off < CPG; off <<= 1)
                sum += __shfl_xor_sync(0xffffffffu, sum, off);
            float mu = sum * (1.0f / CPG);
            float dv = a2[s] - mu;
            float vs = dv * dv;
            #pragma unroll
            for (int off = 1; off < CPG; off <<= 1)
                vs += __shfl_xor_sync(0xffffffffu, vs, off);
            y2 = dv * rsqrtf(vs * (1.0f / CPG) + 1e-5f) * gam2 + bet2;
        }
        a1[s] = y1 + y2;
    }

    #pragma unroll
    for (int s = 0; s < 16; ++s)
        if (s < nv) out[(size_t)(base + s) * COUT + tid] = a1[s];
}

// ---------------- expand compact sums to dense NCDHW ----------------
__global__ void __launch_bounds__(256) k_expand(const float* __restrict__ sum,
                                                float* __restrict__ out) {
    int v0 = blockIdx.x * 1024 + threadIdx.x * 4;
    int cbase = blockIdx.y * 32;
    int rx = g_rank[v0 + 0];
    int ry = g_rank[v0 + 1];
    int rz = g_rank[v0 + 2];
    int rw = g_rank[v0 + 3];
    const float* r0 = (rx >= 0) ? &sum[(size_t)rx * 128] : nullptr;
    const float* r1 = (ry >= 0) ? &sum[(size_t)ry * 128] : nullptr;
    const float* r2 = (rz >= 0) ? &sum[(size_t)rz * 128] : nullptr;
    const float* r3 = (rw >= 0) ? &sum[(size_t)rw * 128] : nullptr;
    #pragma unroll 8
    for (int cc = 0; cc < 32; ++cc) {
        int c = cbase + cc;
        float4 f;
        f.x = r0 ? r0[c] : 0.f;
        f.y = r1 ? r1[c] : 0.f;
        f.z = r2 ? r2[c] : 0.f;
        f.w = r3 ? r3[c] : 0.f;
        __stcs(reinterpret_cast<float4*>(&out[(size_t)c * VOX + v0]), f);
    }
}

// ---------------- launch ----------------
extern "C" void kernel_launch(void* const* d_in, const int* in_sizes, int n_in,
                              void* d_out, int out_size) {
    const float* x   = (const float*)d_in[0];
    const float* W1a = (const float*)d_in[2];
    const float* g1a = (const float*)d_in[3];
    const float* b1a = (const float*)d_in[4];
    const float* W1b = (const float*)d_in[5];
    const float* g1b = (const float*)d_in[6];
    const float* b1b = (const float*)d_in[7];
    const float* W2a = (const float*)d_in[8];
    const float* g2a = (const float*)d_in[9];
    const float* b2a = (const float*)d_in[10];
    const float* W2b = (const float*)d_in[11];
    const float* g2b = (const float*)d_in[12];
    const float* b2b = (const float*)d_in[13];
    float* out = (float*)d_out;

    float *xT, *t1a, *t1b, *ctrA, *ctrB, *poutA, *poutB, *sum;
    float *w1a, *w1b, *w2a, *w2b;
    int *inv0, *inv1, *inv2;
    cudaGetSymbolAddress((void**)&xT,    g_xT);
    cudaGetSymbolAddress((void**)&t1a,   g_t1a);
    cudaGetSymbolAddress((void**)&t1b,   g_t1b);
    cudaGetSymbolAddress((void**)&ctrA,  g_ctrA);
    cudaGetSymbolAddress((void**)&ctrB,  g_ctrB);
    cudaGetSymbolAddress((void**)&poutA, g_poutA);
    cudaGetSymbolAddress((void**)&poutB, g_poutB);
    cudaGetSymbolAddress((void**)&sum,   g_sum);
    cudaGetSymbolAddress((void**)&w1a,   g_w1a);
    cudaGetSymbolAddress((void**)&w1b,   g_w1b);
    cudaGetSymbolAddress((void**)&w2a,   g_w2a);
    cudaGetSymbolAddress((void**)&w2b,   g_w2b);
    cudaGetSymbolAddress((void**)&inv0,  g_inv);
    inv1 = inv0 + (size_t)MAXACT * 8;
    inv2 = inv1 + (size_t)MAXACT * 8;

    const int NB16 = MAXACT / 16;  // 3072

    k_reset<<<1, 32>>>();
    k_transpose<<<VOX / 256, 256>>>(x);
    k_prep_pairs<<<dim3(MAXACT / 256, 3, 8), 256>>>(W1a, W1b, W2a, W2b);

    // stage A: branch1 conv3x3x1 (mode0) + branch2 conv3x1x3 (mode2), then GN+leaky
    k_convAB<64, 0, 2><<<dim3(2048, 2), 64>>>(xT, xT, w1a, w2a, ctrA, ctrB, poutA, poutB);
    k_sumgnA<<<dim3(NB16, 2), 64>>>(ctrA, ctrB, poutA, poutB, inv0, inv2,
                                    g1a, b1a, g2a, b2a, t1a, t1b);
    // stage B: branch1 conv1x3x3 (mode1) + branch2 conv3x3x1 (mode0), then GN, sum=y1+y2
    k_convAB<128, 1, 0><<<dim3(1280, 2), 128>>>(t1a, t1b, w1b, w2b, ctrA, ctrB, poutA, poutB);
    k_sumgnB<<<NB16, 128>>>(ctrA, ctrB, poutA, poutB, inv1, inv0,
                            g1b, b1b, g2b, b2b, sum);

    // expand to dense NCDHW (writes every output element exactly once)
    k_expand<<<dim3(VOX / 1024, 4), 256>>>(sum, out);
}

// round 13
// speedup vs baseline: 1.1722x; 1.1722x over previous
#include <cuda_runtime.h>

#define D_  16
#define H_  128
#define W_  128
#define VOX 262144        // 16*128*128
#define CI  64
#define MAXACT 49152      // cap on active voxels (~39.3K expected)
#define PP  8192          // per-tap pair capacity (~5.9K expected)

// Packed fp32x2 FMA (Blackwell sm_100+; SASS FFMA2). Bitwise == 2x fmaf.
#define FMA2(d, xa, wb, cc) \
    asm("fma.rn.f32x2 %0, %1, %2, %3;" : "=l"(d) : "l"(xa), "l"(wb), "l"(cc))

// ---------------- static device scratch (rank-compacted, two live branches) ----------
__device__ __align__(16) float g_xT[(size_t)MAXACT * CI];
__device__ __align__(16) float g_t1a[(size_t)MAXACT * CI];
__device__ __align__(16) float g_t1b[(size_t)MAXACT * CI];
__device__ __align__(16) float g_ctrA[(size_t)MAXACT * 128];
__device__ __align__(16) float g_ctrB[(size_t)MAXACT * 128];
__device__ __align__(16) float g_poutA[(size_t)8 * PP * 128];
__device__ __align__(16) float g_poutB[(size_t)8 * PP * 128];
__device__ __align__(16) float g_sum[(size_t)MAXACT * 128];
// weights: [tap][ci][co] (co contiguous -> float4 reads over cout)
__device__ __align__(16) float g_w1a[9 * CI * 64];
__device__ __align__(16) float g_w1b[9 * CI * 128];
__device__ __align__(16) float g_w2a[9 * CI * 64];
__device__ __align__(16) float g_w2b[9 * CI * 128];
__device__ int  g_rank[VOX];
__device__ int  g_active[MAXACT];
__device__ int  g_count;
__device__ int  g_pvin[3][8][PP];
__device__ int  g_inv[3][(size_t)MAXACT * 8];
__device__ int  g_pcount[3][8];

// ---------------- reset counters ----------------
__global__ void k_reset() {
    int i = threadIdx.x;
    if (i < 24) (&g_pcount[0][0])[i] = 0;
    if (i == 24) g_count = 0;
}

// ---------------- transpose x -> rank-compact channel-last, build rank map ----------------
__global__ void k_transpose(const float* __restrict__ x) {
    int v = blockIdx.x * blockDim.x + threadIdx.x;
    if (v >= VOX) return;
    bool act = false;
    float4 f[16];
    #pragma unroll
    for (int i = 0; i < 16; ++i) {
        float4 t;
        t.x = x[(size_t)(4 * i + 0) * VOX + v];
        t.y = x[(size_t)(4 * i + 1) * VOX + v];
        t.z = x[(size_t)(4 * i + 2) * VOX + v];
        t.w = x[(size_t)(4 * i + 3) * VOX + v];
        f[i] = t;
        act = act || (t.x != 0.f) || (t.y != 0.f) || (t.z != 0.f) || (t.w != 0.f);
    }
    unsigned ball = __ballot_sync(0xffffffffu, act);
    int rank = -1;
    if (act) {
        int lane = threadIdx.x & 31;
        int leader = __ffs(ball) - 1;
        int base = 0;
        if (lane == leader) base = atomicAdd(&g_count, __popc(ball));
        base = __shfl_sync(ball, base, leader);   // mask == participants: legal
        rank = base + __popc(ball & ((1u << lane) - 1));
        if (rank < MAXACT) {
            g_active[rank] = v;
            #pragma unroll
            for (int i = 0; i < 16; ++i)
                *reinterpret_cast<float4*>(&g_xT[(size_t)rank * CI + 4 * i]) = f[i];
        }
    }
    g_rank[v] = (rank >= 0 && rank < MAXACT) ? rank : -1;
}

// -------- merged: pair lists (grid x,y,z) + weight re-layout (folded by block id) -----
// Weight layout out: [tap][ci][co]
__device__ __forceinline__ void prep_slice(
    const float* __restrict__ s1a, const float* __restrict__ s1b,
    const float* __restrict__ s2a, const float* __restrict__ s2b,
    int idx)
{
    const int N64 = 9 * CI * 64, N128 = 9 * CI * 128;
    const float* src; float* dst; int CO; int k = idx;
    if (k < N64)               { src = s1a; dst = g_w1a; CO = 64; }
    else if ((k -= N64) < N128){ src = s1b; dst = g_w1b; CO = 128; }
    else if ((k -= N128) < N64){ src = s2a; dst = g_w2a; CO = 64; }
    else if ((k -= N64) < N128){ src = s2b; dst = g_w2b; CO = 128; }
    else return;
    int o = k % CO;
    int i = (k / CO) % CI;
    int t = k / (CO * CI);
    dst[k] = src[(o * CI + i) * 9 + t];
}

__global__ void __launch_bounds__(256) k_prep_pairs(
    const float* __restrict__ s1a, const float* __restrict__ s1b,
    const float* __restrict__ s2a, const float* __restrict__ s2b)
{
    __shared__ int s_w[8];
    __shared__ int s_base;
    int mode = blockIdx.y;
    int t8 = blockIdx.z;
    int i = blockIdx.x * 256 + threadIdx.x;
    int N = min(g_count, MAXACT);
    bool valid = i < N;
    int v = valid ? g_active[i] : 0;
    int d = v >> 14, h = (v >> 7) & 127, w = v & 127;
    int wid = threadIdx.x >> 5, lane = threadIdx.x & 31;

    int tap = t8 < 4 ? t8 : t8 + 1;
    int dd, dh, dw;
    if (mode == 0)      { dd = tap / 3 - 1; dh = tap % 3 - 1; dw = 0; }
    else if (mode == 1) { dd = 0;           dh = tap / 3 - 1; dw = tap % 3 - 1; }
    else                { dd = tap / 3 - 1; dh = 0;           dw = tap % 3 - 1; }
    int nd = d + dd, nh = h + dh, nw = w + dw;
    int r2 = -1;
    if (valid && nd >= 0 && nd < D_ && nh >= 0 && nh < H_ && nw >= 0 && nw < W_)
        r2 = g_rank[(nd << 14) | (nh << 7) | nw];
    unsigned ball = __ballot_sync(0xffffffffu, r2 >= 0);
    if (lane == 0) s_w[wid] = __popc(ball);
    __syncthreads();
    if (threadIdx.x == 0) {
        int tot = 0;
        #pragma unroll
        for (int k = 0; k < 8; ++k) { int c = s_w[k]; s_w[k] = tot; tot += c; }
        s_base = tot ? atomicAdd(&g_pcount[mode][t8], tot) : 0;
    }
    __syncthreads();
    int pos = -1;
    if (r2 >= 0) {
        pos = s_base + s_w[wid] + __popc(ball & ((1u << lane) - 1));
        if (pos >= 0 && pos < PP) g_pvin[mode][t8][pos] = r2;
        else pos = -1;
    }
    if (valid) g_inv[mode][(size_t)i * 8 + t8] = pos;

    // folded weight prep: linear block id handles 256 elems each
    int bid = blockIdx.x + gridDim.x * (blockIdx.y + 3 * blockIdx.z);
    const int PREP_TOTAL = 9 * CI * (64 + 128 + 64 + 128);   // 221184
    int pidx = bid * 256 + threadIdx.x;
    if (pidx < PREP_TOTAL) prep_slice(s1a, s1b, s2a, s2b, pidx);
}

// ---------- register-tiled two-branch conv: grid = (chunks, 9 taps, 2 branches) ------
// Thread (co4, vg) owns 4 couts x 8 voxels. Per cin: 3 LDS.128 + 16 FFMA2.
template<int COUT, int MA, int MB>
__global__ void __launch_bounds__(COUT) k_convAB(
    const float* __restrict__ in0, const float* __restrict__ in1,
    const float* __restrict__ wA,  const float* __restrict__ wB,
    float* __restrict__ ctr0, float* __restrict__ ctr1,
    float* __restrict__ pout0, float* __restrict__ pout1)
{
    constexpr int NCO4 = COUT / 4;
    __shared__ __align__(16) float s_in[CI][32];
    __shared__ int s_vi[32];
    const int tid = threadIdx.x;
    const int t8 = blockIdx.y;
    const int branch = blockIdx.z;
    const int mode = branch ? MB : MA;
    const bool center = (t8 == 8);
    const int tap = center ? 4 : (t8 < 4 ? t8 : t8 + 1);
    const int m = center ? min(g_count, MAXACT) : min(g_pcount[mode][t8], PP);
    const int base = blockIdx.x * 32;
    if (base >= m) return;
    const int nv = min(32, m - base);
    const float* __restrict__ in = branch ? in1 : in0;
    const float* __restrict__ w = (branch ? wB : wA) + (size_t)tap * CI * COUT;
    float* __restrict__ dst = center ? (branch ? ctr1 : ctr0)
                                     : (branch ? pout1 : pout0) + (size_t)t8 * PP * COUT;

    if (tid < 32) {
        int r = 0;
        if (tid < nv) {
            if (center) r = base + tid;
            else {
                r = g_pvin[mode][t8][base + tid];
                r = min(max(r, 0), MAXACT - 1);   // hardening
            }
        }
        s_vi[tid] = r;
    }
    __syncthreads();

    // gather 32 rows x 64 ch; slot = low bits -> conflict-free STS
    for (int e = tid; e < 32 * (CI / 4); e += COUT) {
        int slot = e & 31, q = e >> 5;
        float4 f = make_float4(0.f, 0.f, 0.f, 0.f);
        if (slot < nv)
            f = *reinterpret_cast<const float4*>(&in[(size_t)s_vi[slot] * CI + q * 4]);
        s_in[q * 4 + 0][slot] = f.x;
        s_in[q * 4 + 1][slot] = f.y;
        s_in[q * 4 + 2][slot] = f.z;
        s_in[q * 4 + 3][slot] = f.w;
    }
    __syncthreads();

    const int co4 = tid % NCO4;          // cout group (4 couts)
    const int vg  = tid / NCO4;          // voxel group (8 voxels)

    unsigned long long acc[4][4];        // [co][voxpair]
    #pragma unroll
    for (int c = 0; c < 4; ++c)
        #pragma unroll
        for (int p = 0; p < 4; ++p) acc[c][p] = 0ull;

    const float4* __restrict__ w4 = reinterpret_cast<const float4*>(w);
    union Q4 { float4 f4; unsigned long long u[2]; };

    #pragma unroll 4
    for (int cin = 0; cin < CI; ++cin) {
        float4 wv = w4[cin * NCO4 + co4];
        Q4 xa, xb;
        xa.f4 = *reinterpret_cast<const float4*>(&s_in[cin][vg * 8]);
        xb.f4 = *reinterpret_cast<const float4*>(&s_in[cin][vg * 8 + 4]);
        unsigned long long xr[4] = { xa.u[0], xa.u[1], xb.u[0], xb.u[1] };
        #pragma unroll
        for (int c = 0; c < 4; ++c) {
            float wc = (c == 0) ? wv.x : (c == 1) ? wv.y : (c == 2) ? wv.z : wv.w;
            unsigned long long w2;
            asm("mov.b64 %0, {%1, %1};" : "=l"(w2) : "f"(wc));
            FMA2(acc[c][0], xr[0], w2, acc[c][0]);
            FMA2(acc[c][1], xr[1], w2, acc[c][1]);
            FMA2(acc[c][2], xr[2], w2, acc[c][2]);
            FMA2(acc[c][3], xr[3], w2, acc[c][3]);
        }
    }

    // store: per voxel one STG.128 of 4 consecutive couts
    union P2 { unsigned long long u; float f[2]; };
    #pragma unroll
    for (int v = 0; v < 8; ++v) {
        int s = vg * 8 + v;
        if (s < nv) {
            int vp = v >> 1, k = v & 1;
            P2 p0, p1, p2, p3;
            p0.u = acc[0][vp]; p1.u = acc[1][vp];
            p2.u = acc[2][vp]; p3.u = acc[3][vp];
            float4 o = make_float4(p0.f[k], p1.f[k], p2.f[k], p3.f[k]);
            *reinterpret_cast<float4*>(&dst[(size_t)(base + s) * COUT + co4 * 4]) = o;
        }
    }
}

// ---------------- stage-a merged sum+GN+leaky: grid = (chunks, 2 branches) ----------
__global__ void __launch_bounds__(64) k_sumgnA(
    const float* __restrict__ ctr0, const float* __restrict__ ctr1,
    const float* __restrict__ pout0, const float* __restrict__ pout1,
    const int* __restrict__ invA, const int* __restrict__ invB,
    const float* __restrict__ gA, const float* __restrict__ bA,
    const float* __restrict__ gB, const float* __restrict__ bB,
    float* __restrict__ outA, float* __restrict__ outB)
{
    constexpr int COUT = 64, CPG = 2;
    __shared__ int s_inv[128];
    const int tid = threadIdx.x;
    const int branch = blockIdx.y;
    const int N = min(g_count, MAXACT);
    const int base = blockIdx.x * 16;
    if (base >= N) return;
    const int nv = min(16, N - base);
    const float* __restrict__ ctr = branch ? ctr1 : ctr0;
    const float* __restrict__ pout = branch ? pout1 : pout0;
    const int* __restrict__ inv = branch ? invB : invA;
    const float gam = (branch ? gB : gA)[tid];
    const float bet = (branch ? bB : bA)[tid];
    float* __restrict__ out = branch ? outB : outA;

    for (int e = tid; e < 128; e += COUT) {
        int s = e >> 3, t8e = e & 7;
        s_inv[e] = (s < nv) ? inv[(size_t)(base + s) * 8 + t8e] : -1;
    }
    __syncthreads();

    float a[16];
    #pragma unroll
    for (int s = 0; s < 16; ++s)
        a[s] = (s < nv) ? ctr[(size_t)(base + s) * COUT + tid] : 0.f;

    #pragma unroll
    for (int t8 = 0; t8 < 8; ++t8) {
        #pragma unroll
        for (int s = 0; s < 16; ++s) {
            int p = s_inv[s * 8 + t8];
            if (p >= 0 && p < PP)
                a[s] += pout[((size_t)t8 * PP + p) * COUT + tid];
        }
    }

    #pragma unroll
    for (int s = 0; s < 16; ++s) {
        float sum = a[s];
        #pragma unroll
        for (int off = 1; off < CPG; off <<= 1)
            sum += __shfl_xor_sync(0xffffffffu, sum, off);
        float mu = sum * (1.0f / CPG);
        float dv = a[s] - mu;
        float vs = dv * dv;
        #pragma unroll
        for (int off = 1; off < CPG; off <<= 1)
            vs += __shfl_xor_sync(0xffffffffu, vs, off);
        float y = dv * rsqrtf(vs * (1.0f / CPG) + 1e-5f) * gam + bet;
        a[s] = (y > 0.f) ? y : 0.01f * y;   // leaky
    }

    #pragma unroll
    for (int s = 0; s < 16; ++s)
        if (s < nv) out[(size_t)(base + s) * COUT + tid] = a[s];
}

// ---------------- stage-b fused: both branches' sum+GN, write sum = y1+y2 ------------
__global__ void __launch_bounds__(128) k_sumgnB(
    const float* __restrict__ ctr0, const float* __restrict__ ctr1,
    const float* __restrict__ pout0, const float* __restrict__ pout1,
    const int* __restrict__ invA, const int* __restrict__ invB,
    const float* __restrict__ gA, const float* __restrict__ bA,
    const float* __restrict__ gB, const float* __restrict__ bB,
    float* __restrict__ out)
{
    constexpr int COUT = 128, CPG = 4;
    __shared__ int s_invA[128];
    __shared__ int s_invB[128];
    const int tid = threadIdx.x;
    const int N = min(g_count, MAXACT);
    const int base = blockIdx.x * 16;
    if (base >= N) return;
    const int nv = min(16, N - base);
    const float gam1 = gA[tid], bet1 = bA[tid];
    const float gam2 = gB[tid], bet2 = bB[tid];

    for (int e = tid; e < 128; e += COUT) {
        int s = e >> 3, t8e = e & 7;
        s_invA[e] = (s < nv) ? invA[(size_t)(base + s) * 8 + t8e] : -1;
        s_invB[e] = (s < nv) ? invB[(size_t)(base + s) * 8 + t8e] : -1;
    }
    __syncthreads();

    float a1[16], a2[16];
    #pragma unroll
    for (int s = 0; s < 16; ++s) {
        a1[s] = (s < nv) ? ctr0[(size_t)(base + s) * COUT + tid] : 0.f;
        a2[s] = (s < nv) ? ctr1[(size_t)(base + s) * COUT + tid] : 0.f;
    }

    #pragma unroll
    for (int t8 = 0; t8 < 8; ++t8) {
        #pragma unroll
        for (int s = 0; s < 16; ++s) {
            int p = s_invA[s * 8 + t8];
            if (p >= 0 && p < PP)
                a1[s] += pout0[((size_t)t8 * PP + p) * COUT + tid];
            int q = s_invB[s * 8 + t8];
            if (q >= 0 && q < PP)
                a2[s] += pout1[((size_t)t8 * PP + q) * COUT + tid];
        }
    }

    #pragma unroll
    for (int s = 0; s < 16; ++s) {
        float y1, y2;
        {
            float sum = a1[s];
            #pragma unroll
            for (int off = 1; off < CPG; off <<= 1)
                sum += __shfl_xor_sync(0xffffffffu, sum, off);
            float mu = sum * (1.0f / CPG);
            float dv = a1[s] - mu;
            float vs = dv * dv;
            #pragma unroll
            for (int off = 1; off < CPG; off <<= 1)
                vs += __shfl_xor_sync(0xffffffffu, vs, off);
            y1 = dv * rsqrtf(vs * (1.0f / CPG) + 1e-5f) * gam1 + bet1;
        }
        {
            float sum = a2[s];
            #pragma unroll
            for (int off = 1; off < CPG; off <<= 1)
                sum += __shfl_xor_sync(0xffffffffu, sum, off);
            float mu = sum * (1.0f / CPG);
            float dv = a2[s] - mu;
            float vs = dv * dv;
            #pragma unroll
            for (int off = 1; off < CPG; off <<= 1)
                vs += __shfl_xor_sync(0xffffffffu, vs, off);
            y2 = dv * rsqrtf(vs * (1.0f / CPG) + 1e-5f) * gam2 + bet2;
        }
        a1[s] = y1 + y2;
    }

    #pragma unroll
    for (int s = 0; s < 16; ++s)
        if (s < nv) out[(size_t)(base + s) * COUT + tid] = a1[s];
}

// ---------------- expand compact sums to dense NCDHW ----------------
__global__ void __launch_bounds__(256) k_expand(const float* __restrict__ sum,
                                                float* __restrict__ out) {
    int v0 = blockIdx.x * 1024 + threadIdx.x * 4;
    int cbase = blockIdx.y * 32;
    int rx = g_rank[v0 + 0];
    int ry = g_rank[v0 + 1];
    int rz = g_rank[v0 + 2];
    int rw = g_rank[v0 + 3];
    const float* r0 = (rx >= 0) ? &sum[(size_t)rx * 128] : nullptr;
    const float* r1 = (ry >= 0) ? &sum[(size_t)ry * 128] : nullptr;
    const float* r2 = (rz >= 0) ? &sum[(size_t)rz * 128] : nullptr;
    const float* r3 = (rw >= 0) ? &sum[(size_t)rw * 128] : nullptr;
    #pragma unroll 8
    for (int cc = 0; cc < 32; ++cc) {
        int c = cbase + cc;
        float4 f;
        f.x = r0 ? r0[c] : 0.f;
        f.y = r1 ? r1[c] : 0.f;
        f.z = r2 ? r2[c] : 0.f;
        f.w = r3 ? r3[c] : 0.f;
        __stcs(reinterpret_cast<float4*>(&out[(size_t)c * VOX + v0]), f);
    }
}

// ---------------- launch ----------------
extern "C" void kernel_launch(void* const* d_in, const int* in_sizes, int n_in,
                              void* d_out, int out_size) {
    const float* x   = (const float*)d_in[0];
    const float* W1a = (const float*)d_in[2];
    const float* g1a = (const float*)d_in[3];
    const float* b1a = (const float*)d_in[4];
    const float* W1b = (const float*)d_in[5];
    const float* g1b = (const float*)d_in[6];
    const float* b1b = (const float*)d_in[7];
    const float* W2a = (const float*)d_in[8];
    const float* g2a = (const float*)d_in[9];
    const float* b2a = (const float*)d_in[10];
    const float* W2b = (const float*)d_in[11];
    const float* g2b = (const float*)d_in[12];
    const float* b2b = (const float*)d_in[13];
    float* out = (float*)d_out;

    float *xT, *t1a, *t1b, *ctrA, *ctrB, *poutA, *poutB, *sum;
    float *w1a, *w1b, *w2a, *w2b;
    int *inv0, *inv1, *inv2;
    cudaGetSymbolAddress((void**)&xT,    g_xT);
    cudaGetSymbolAddress((void**)&t1a,   g_t1a);
    cudaGetSymbolAddress((void**)&t1b,   g_t1b);
    cudaGetSymbolAddress((void**)&ctrA,  g_ctrA);
    cudaGetSymbolAddress((void**)&ctrB,  g_ctrB);
    cudaGetSymbolAddress((void**)&poutA, g_poutA);
    cudaGetSymbolAddress((void**)&poutB, g_poutB);
    cudaGetSymbolAddress((void**)&sum,   g_sum);
    cudaGetSymbolAddress((void**)&w1a,   g_w1a);
    cudaGetSymbolAddress((void**)&w1b,   g_w1b);
    cudaGetSymbolAddress((void**)&w2a,   g_w2a);
    cudaGetSymbolAddress((void**)&w2b,   g_w2b);
    cudaGetSymbolAddress((void**)&inv0,  g_inv);
    inv1 = inv0 + (size_t)MAXACT * 8;
    inv2 = inv1 + (size_t)MAXACT * 8;

    const int NB32 = MAXACT / 32;  // 1536
    const int NB16 = MAXACT / 16;  // 3072

    k_reset<<<1, 32>>>();
    k_transpose<<<VOX / 256, 256>>>(x);
    k_prep_pairs<<<dim3(MAXACT / 256, 3, 8), 256>>>(W1a, W1b, W2a, W2b);

    // stage A: branch1 conv3x3x1 (mode0) + branch2 conv3x1x3 (mode2), then GN+leaky
    k_convAB<64, 0, 2><<<dim3(NB32, 9, 2), 64>>>(xT, xT, w1a, w2a, ctrA, ctrB, poutA, poutB);
    k_sumgnA<<<dim3(NB16, 2), 64>>>(ctrA, ctrB, poutA, poutB, inv0, inv2,
                                    g1a, b1a, g2a, b2a, t1a, t1b);
    // stage B: branch1 conv1x3x3 (mode1) + branch2 conv3x3x1 (mode0), then GN, sum=y1+y2
    k_convAB<128, 1, 0><<<dim3(NB32, 9, 2), 128>>>(t1a, t1b, w1b, w2b, ctrA, ctrB, poutA, poutB);
    k_sumgnB<<<NB16, 128>>>(ctrA, ctrB, poutA, poutB, inv1, inv0,
                            g1b, b1b, g2b, b2b, sum);

    // expand to dense NCDHW (writes every output element exactly once)
    k_expand<<<dim3(VOX / 1024, 4), 256>>>(sum, out);
}